// round 3
// baseline (speedup 1.0000x reference)
#include <cuda_runtime.h>
#include <stdint.h>

#define N_NODES 50000
#define N_EDGES 1000000
#define F_IN  64
#define F_HID 64
#define F_OUT 32

// Scratch (allocation-free rule: device globals)
__device__ __align__(16) float g_deg [N_NODES];
__device__ __align__(16) float g_hs1 [N_NODES * F_HID];
__device__ __align__(16) float g_acc1[N_NODES * F_HID];
__device__ __align__(16) float g_hs2 [N_NODES * F_OUT];
__device__ __align__(16) float g_acc2[N_NODES * F_OUT];
__device__ int g_idx64;   // 1 if edge_index is int64, 0 if int32

__device__ __forceinline__ void red_add_v4(float* a, float4 v) {
    asm volatile("red.global.add.v4.f32 [%0], {%1, %2, %3, %4};"
                 :: "l"(a), "f"(v.x), "f"(v.y), "f"(v.z), "f"(v.w)
                 : "memory");
}

// Fetch edge endpoint: half=0 -> src row, half=1 -> dst row.
__device__ __forceinline__ int edge_idx(const void* ei, int half, int e) {
    if (g_idx64) {
        const long long* p = (const long long*)ei;
        return (int)p[half * N_EDGES + e];
    } else {
        const int* p = (const int*)ei;
        return p[half * N_EDGES + e];
    }
}

// ---------------------------------------------------------------- dtype detect
// int64 values < 50000 => every odd 32-bit word (LE high word) is 0.
// int32 random values in [0,50000) => essentially impossible that 2048 are all 0.
__global__ void k_detect(const int* __restrict__ ei32) {
    __shared__ int any_nonzero;
    if (threadIdx.x == 0) any_nonzero = 0;
    __syncthreads();
    for (int i = threadIdx.x; i < 2048; i += blockDim.x)
        if (ei32[2 * i + 1] != 0) any_nonzero = 1;
    __syncthreads();
    if (threadIdx.x == 0) g_idx64 = any_nonzero ? 0 : 1;
}

// ---------------------------------------------------------------- deg
__global__ void k_init_deg() {
    int i = blockIdx.x * blockDim.x + threadIdx.x;
    if (i < N_NODES) g_deg[i] = 1.0f;   // self-loop folded in
}

__global__ void k_deg(const void* __restrict__ ei) {
    int i = blockIdx.x * blockDim.x + threadIdx.x;
    if (i < N_EDGES) atomicAdd(&g_deg[edge_idx(ei, 1, i)], 1.0f);
}

// ---------------------------------------------------------------- GEMM1: hs1 = (X @ W1) * dinv ; acc1 = hs1
__global__ void __launch_bounds__(256) k_gemm1(const float* __restrict__ x,
                                               const float* __restrict__ W) {
    __shared__ float Ws[F_IN * F_HID];       // 16 KB
    __shared__ float Xs[64][F_IN + 1];       // 16.25 KB, pad to kill bank conflicts
    int t = threadIdx.x;
    int row0 = blockIdx.x * 64;

    for (int i = t; i < F_IN * F_HID; i += 256) Ws[i] = W[i];

    #pragma unroll
    for (int i = 0; i < 4; i++) {
        int idx = t + i * 256;               // 0..1023 float4 slots
        int r = idx >> 4, c = (idx & 15) * 4;
        float4 v = make_float4(0.f, 0.f, 0.f, 0.f);
        if (row0 + r < N_NODES)
            v = *(const float4*)(x + (row0 + r) * F_IN + c);
        Xs[r][c + 0] = v.x; Xs[r][c + 1] = v.y;
        Xs[r][c + 2] = v.z; Xs[r][c + 3] = v.w;
    }
    __syncthreads();

    int cb = (t & 15) * 4;                   // 16 col-groups of 4
    int rb = (t >> 4) * 4;                   // 16 row-groups of 4
    float4 acc[4];
    #pragma unroll
    for (int i = 0; i < 4; i++) acc[i] = make_float4(0.f, 0.f, 0.f, 0.f);

    #pragma unroll
    for (int k = 0; k < F_IN; k++) {
        float4 w = *(const float4*)&Ws[k * F_HID + cb];
        #pragma unroll
        for (int i = 0; i < 4; i++) {
            float xv = Xs[rb + i][k];
            acc[i].x += xv * w.x; acc[i].y += xv * w.y;
            acc[i].z += xv * w.z; acc[i].w += xv * w.w;
        }
    }

    #pragma unroll
    for (int i = 0; i < 4; i++) {
        int r = row0 + rb + i;
        if (r < N_NODES) {
            float s = rsqrtf(g_deg[r]);
            float4 v = make_float4(acc[i].x * s, acc[i].y * s,
                                   acc[i].z * s, acc[i].w * s);
            *(float4*)(g_hs1  + r * F_HID + cb) = v;
            *(float4*)(g_acc1 + r * F_HID + cb) = v;   // self-loop init
        }
    }
}

// ---------------------------------------------------------------- scatter1: acc1[dst] += hs1[src]  (64 wide)
__global__ void __launch_bounds__(256) k_scatter1(const void* __restrict__ ei) {
    unsigned gid = blockIdx.x * 256u + threadIdx.x;   // 16M threads exactly
    unsigned e = gid >> 4;
    int c = (gid & 15) * 4;
    int s = edge_idx(ei, 0, e);
    int d = edge_idx(ei, 1, e);
    float4 v = *(const float4*)(g_hs1 + s * F_HID + c);
    red_add_v4(g_acc1 + d * F_HID + c, v);
}

// ---------------------------------------------------------------- GEMM2: x2 = relu(dinv*acc1 + b1); hs2 = (x2 @ W2)*dinv; acc2 = hs2
__global__ void __launch_bounds__(256) k_gemm2(const float* __restrict__ W,
                                               const float* __restrict__ b1) {
    __shared__ float Ws[F_HID * F_OUT];      // 8 KB
    __shared__ float Xs[128][F_HID + 1];     // 32.5 KB
    int t = threadIdx.x;
    int row0 = blockIdx.x * 128;

    for (int i = t; i < F_HID * F_OUT; i += 256) Ws[i] = W[i];

    #pragma unroll
    for (int i = 0; i < 8; i++) {
        int idx = t + i * 256;               // 0..2047 float4 slots
        int r = idx >> 4, c = (idx & 15) * 4;
        int gr = row0 + r;
        float4 v = make_float4(0.f, 0.f, 0.f, 0.f);
        if (gr < N_NODES) {
            float s = rsqrtf(g_deg[gr]);
            float4 a  = *(const float4*)(g_acc1 + gr * F_HID + c);
            float4 bb = *(const float4*)(b1 + c);
            v.x = fmaxf(fmaf(a.x, s, bb.x), 0.f);
            v.y = fmaxf(fmaf(a.y, s, bb.y), 0.f);
            v.z = fmaxf(fmaf(a.z, s, bb.z), 0.f);
            v.w = fmaxf(fmaf(a.w, s, bb.w), 0.f);
        }
        Xs[r][c + 0] = v.x; Xs[r][c + 1] = v.y;
        Xs[r][c + 2] = v.z; Xs[r][c + 3] = v.w;
    }
    __syncthreads();

    int cb = (t & 7) * 4;                    // 8 col-groups of 4 -> 32 cols
    int rb = (t >> 3) * 4;                   // 32 row-groups of 4 -> 128 rows
    float4 acc[4];
    #pragma unroll
    for (int i = 0; i < 4; i++) acc[i] = make_float4(0.f, 0.f, 0.f, 0.f);

    #pragma unroll
    for (int k = 0; k < F_HID; k++) {
        float4 w = *(const float4*)&Ws[k * F_OUT + cb];
        #pragma unroll
        for (int i = 0; i < 4; i++) {
            float xv = Xs[rb + i][k];
            acc[i].x += xv * w.x; acc[i].y += xv * w.y;
            acc[i].z += xv * w.z; acc[i].w += xv * w.w;
        }
    }

    #pragma unroll
    for (int i = 0; i < 4; i++) {
        int r = row0 + rb + i;
        if (r < N_NODES) {
            float s = rsqrtf(g_deg[r]);
            float4 v = make_float4(acc[i].x * s, acc[i].y * s,
                                   acc[i].z * s, acc[i].w * s);
            *(float4*)(g_hs2  + r * F_OUT + cb) = v;
            *(float4*)(g_acc2 + r * F_OUT + cb) = v;   // self-loop init
        }
    }
}

// ---------------------------------------------------------------- scatter2: acc2[dst] += hs2[src]  (32 wide)
__global__ void __launch_bounds__(256) k_scatter2(const void* __restrict__ ei) {
    unsigned gid = blockIdx.x * 256u + threadIdx.x;   // 8M threads exactly
    unsigned e = gid >> 3;
    int c = (gid & 7) * 4;
    int s = edge_idx(ei, 0, e);
    int d = edge_idx(ei, 1, e);
    float4 v = *(const float4*)(g_hs2 + s * F_OUT + c);
    red_add_v4(g_acc2 + d * F_OUT + c, v);
}

// ---------------------------------------------------------------- finish: out = dinv*acc2 + b2
__global__ void k_finish(float* __restrict__ out, const float* __restrict__ b2) {
    int gid = blockIdx.x * blockDim.x + threadIdx.x;  // N_NODES * 8 float4
    if (gid < N_NODES * (F_OUT / 4)) {
        int r = gid >> 3;
        int c = (gid & 7) * 4;
        float s = rsqrtf(g_deg[r]);
        float4 a  = *(const float4*)(g_acc2 + r * F_OUT + c);
        float4 bb = *(const float4*)(b2 + c);
        float4 v = make_float4(fmaf(a.x, s, bb.x), fmaf(a.y, s, bb.y),
                               fmaf(a.z, s, bb.z), fmaf(a.w, s, bb.w));
        *(float4*)(out + r * F_OUT + c) = v;
    }
}

// ----------------------------------------------------------------
extern "C" void kernel_launch(void* const* d_in, const int* in_sizes, int n_in,
                              void* d_out, int out_size) {
    const float* x  = (const float*)d_in[0];
    const void*  ei = d_in[1];
    const float* W1 = (const float*)d_in[2];
    const float* b1 = (const float*)d_in[3];
    const float* W2 = (const float*)d_in[4];
    const float* b2 = (const float*)d_in[5];

    k_detect<<<1, 256>>>((const int*)ei);
    k_init_deg<<<(N_NODES + 255) / 256, 256>>>();
    k_deg<<<(N_EDGES + 255) / 256, 256>>>(ei);
    k_gemm1<<<(N_NODES + 63) / 64, 256>>>(x, W1);
    k_scatter1<<<(N_EDGES * 16) / 256, 256>>>(ei);     // 62500 blocks
    k_gemm2<<<(N_NODES + 127) / 128, 256>>>(W2, b1);
    k_scatter2<<<(N_EDGES * 8) / 256, 256>>>(ei);      // 31250 blocks
    k_finish<<<(N_NODES * (F_OUT / 4) + 255) / 256, 256>>>((float*)d_out, b2);
}